// round 9
// baseline (speedup 1.0000x reference)
#include <cuda_runtime.h>
#include <cstdint>

#define B_ROWS 8192
#define C_ROWS 10000
#define D_DIM  512
#define WARPS_PER_CTA 8
#define GRID_CTAS 512                       // 512 CTAs x 8 warps x 2 rows = 8192
#define ROW_STRIDE 4096                     // second row of each warp

// ---------------------------------------------------------------------------
// Fused kernel, 2 rows per warp. No shared memory, no __syncthreads:
// each warp independently reduces its two rows and lane 0 atomically
// accumulates into the output. Warps retire as soon as they finish.
// ---------------------------------------------------------------------------
__global__ __launch_bounds__(256, 4)
void center_loss_fused(const float* __restrict__ x,
                       const void*  __restrict__ labels,
                       const float* __restrict__ centers,
                       float* __restrict__ out)
{
    const int t    = threadIdx.x;
    const int warp = t >> 5;
    const int lane = t & 31;

    const int gw   = blockIdx.x * WARPS_PER_CTA + warp;  // 0..4095
    const int row0 = gw;
    const int row1 = gw + ROW_STRIDE;

    // ---- issue everything label-independent FIRST ----
    // dtype-detect word (first 8 u64 words: in-bounds for both i32/i64
    // layouts; genuine i64 labels <10000 => every word <10000; packed i32
    // pairs exceed 2^32 whenever the odd-index label != 0).
    unsigned long long dw = ((const unsigned long long*)labels)[lane & 7];
    // int32 interpretation of both labels: ALWAYS in-bounds, load now.
    int l32_0 = ((const int*)labels)[row0];
    int l32_1 = ((const int*)labels)[row1];

    // x loads for both rows: independent of labels, issue all 8 now.
    const float4* __restrict__ xr0 =
        reinterpret_cast<const float4*>(x + (size_t)row0 * D_DIM);
    const float4* __restrict__ xr1 =
        reinterpret_cast<const float4*>(x + (size_t)row1 * D_DIM);
    float4 a00 = xr0[lane];       float4 a01 = xr0[lane + 32];
    float4 a02 = xr0[lane + 64];  float4 a03 = xr0[lane + 96];
    float4 a10 = xr1[lane];       float4 a11 = xr1[lane + 32];
    float4 a12 = xr1[lane + 64];  float4 a13 = xr1[lane + 96];

    // ---- resolve labels ----
    unsigned big = __ballot_sync(0xFFFFFFFFu, dw >= (unsigned long long)C_ROWS);
    long long lbl0, lbl1;
    if (big == 0u) {   // genuine int64 (rare path: one extra dependent load)
        lbl0 = ((const long long*)labels)[row0];
        lbl1 = ((const long long*)labels)[row1];
    } else {           // int32 (already in flight/arrived)
        lbl0 = (long long)l32_0;
        lbl1 = (long long)l32_1;
    }

    const float4* __restrict__ cr0 =
        reinterpret_cast<const float4*>(centers + (size_t)lbl0 * D_DIM);
    const float4* __restrict__ cr1 =
        reinterpret_cast<const float4*>(centers + (size_t)lbl1 * D_DIM);

    // ---- row 0 ----
    float4 c0 = cr0[lane];
    float4 c1 = cr0[lane + 32];
    float4 c2 = cr0[lane + 64];
    float4 c3 = cr0[lane + 96];

    float s0 = 0.0f, d;
    d = a00.x - c0.x; s0 = fmaf(d, d, s0);
    d = a00.y - c0.y; s0 = fmaf(d, d, s0);
    d = a00.z - c0.z; s0 = fmaf(d, d, s0);
    d = a00.w - c0.w; s0 = fmaf(d, d, s0);
    d = a01.x - c1.x; s0 = fmaf(d, d, s0);
    d = a01.y - c1.y; s0 = fmaf(d, d, s0);
    d = a01.z - c1.z; s0 = fmaf(d, d, s0);
    d = a01.w - c1.w; s0 = fmaf(d, d, s0);
    d = a02.x - c2.x; s0 = fmaf(d, d, s0);
    d = a02.y - c2.y; s0 = fmaf(d, d, s0);
    d = a02.z - c2.z; s0 = fmaf(d, d, s0);
    d = a02.w - c2.w; s0 = fmaf(d, d, s0);
    d = a03.x - c3.x; s0 = fmaf(d, d, s0);
    d = a03.y - c3.y; s0 = fmaf(d, d, s0);
    d = a03.z - c3.z; s0 = fmaf(d, d, s0);
    d = a03.w - c3.w; s0 = fmaf(d, d, s0);

    // ---- row 1 ----
    c0 = cr1[lane];
    c1 = cr1[lane + 32];
    c2 = cr1[lane + 64];
    c3 = cr1[lane + 96];

    float s1 = 0.0f;
    d = a10.x - c0.x; s1 = fmaf(d, d, s1);
    d = a10.y - c0.y; s1 = fmaf(d, d, s1);
    d = a10.z - c0.z; s1 = fmaf(d, d, s1);
    d = a10.w - c0.w; s1 = fmaf(d, d, s1);
    d = a11.x - c1.x; s1 = fmaf(d, d, s1);
    d = a11.y - c1.y; s1 = fmaf(d, d, s1);
    d = a11.z - c1.z; s1 = fmaf(d, d, s1);
    d = a11.w - c1.w; s1 = fmaf(d, d, s1);
    d = a12.x - c2.x; s1 = fmaf(d, d, s1);
    d = a12.y - c2.y; s1 = fmaf(d, d, s1);
    d = a12.z - c2.z; s1 = fmaf(d, d, s1);
    d = a12.w - c2.w; s1 = fmaf(d, d, s1);
    d = a13.x - c3.x; s1 = fmaf(d, d, s1);
    d = a13.y - c3.y; s1 = fmaf(d, d, s1);
    d = a13.z - c3.z; s1 = fmaf(d, d, s1);
    d = a13.w - c3.w; s1 = fmaf(d, d, s1);

    // ---- two independent warp reductions (per-row clamp stays separate) ----
    #pragma unroll
    for (int off = 16; off > 0; off >>= 1) {
        s0 += __shfl_xor_sync(0xFFFFFFFFu, s0, off);
        s1 += __shfl_xor_sync(0xFFFFFFFFu, s1, off);
    }

    // ---- per-warp finish: clamp both rows, one atomic per warp ----
    if (lane == 0) {
        float d0 = fminf(fmaxf(s0, 1e-12f), 1e12f);
        float d1 = fminf(fmaxf(s1, 1e-12f), 1e12f);
        atomicAdd(out, (d0 + d1) * (1.0f / (float)B_ROWS));
    }
}

// ---------------------------------------------------------------------------
// Launch. Inputs identified BY SIZE (robust to metadata ordering):
//   x: 4,194,304 f32 | labels: 8,192 (i32/i64, device-detected) |
//   centers: 5,120,000 f32. Output: scalar f32 (atomic-accumulated).
// ---------------------------------------------------------------------------
extern "C" void kernel_launch(void* const* d_in, const int* in_sizes, int n_in,
                              void* d_out, int out_size)
{
    const float* x       = nullptr;
    const void*  labels  = nullptr;
    const float* centers = nullptr;

    for (int i = 0; i < n_in; i++) {
        if (in_sizes[i] == B_ROWS * D_DIM)       x       = (const float*)d_in[i];
        else if (in_sizes[i] == B_ROWS)          labels  = d_in[i];
        else if (in_sizes[i] == C_ROWS * D_DIM)  centers = (const float*)d_in[i];
    }

    float* out = (float*)d_out;

    cudaMemsetAsync(out, 0, sizeof(float));   // zero accumulator each replay
    center_loss_fused<<<GRID_CTAS, 32 * WARPS_PER_CTA>>>(x, labels, centers, out);
}

// round 10
// speedup vs baseline: 1.2915x; 1.2915x over previous
#include <cuda_runtime.h>
#include <cstdint>

#define B_ROWS 8192
#define C_ROWS 10000
#define D_DIM  512
#define WARPS_PER_CTA 8
#define GRID_CTAS (B_ROWS / WARPS_PER_CTA)   // 1024, warp-per-row

// ---------------------------------------------------------------------------
// Warp-per-row fused kernel (highest-occupancy shape = bench-best so far),
// with the serial detect head removed: per-warp ballot dtype detect and
// label loads issued concurrently with the x-row loads.
// ---------------------------------------------------------------------------
__global__ __launch_bounds__(256, 7)
void center_loss_fused(const float* __restrict__ x,
                       const void*  __restrict__ labels,
                       const float* __restrict__ centers,
                       float* __restrict__ out)
{
    __shared__ float s_part[WARPS_PER_CTA];

    const int t    = threadIdx.x;
    const int warp = t >> 5;
    const int lane = t & 31;

    const int row = blockIdx.x * WARPS_PER_CTA + warp;   // 0..8191

    // ---- head: issue everything label-independent FIRST, no barriers ----
    // dtype-detect word: first 8 u64-interpreted words (64 B, in-bounds for
    // both 8192*i32 and 8192*i64 layouts). Genuine i64 labels < 10000 keep
    // every word < 10000; a packed i32 pair exceeds 2^32 whenever the
    // odd-index label != 0 (checked over 16 labels -> certain in practice).
    unsigned long long dw = ((const unsigned long long*)labels)[lane & 7];
    // int32 interpretation: ALWAYS in-bounds, issue now (likely path).
    int l32 = ((const int*)labels)[row];

    // x row: 4 float4 per lane, label-independent, issue all now.
    const float4* __restrict__ xr =
        reinterpret_cast<const float4*>(x + (size_t)row * D_DIM);
    float4 a0 = xr[lane];
    float4 a1 = xr[lane + 32];
    float4 a2 = xr[lane + 64];
    float4 a3 = xr[lane + 96];

    // ---- resolve label (per-warp ballot; no __syncthreads) ----
    unsigned big = __ballot_sync(0xFFFFFFFFu, dw >= (unsigned long long)C_ROWS);
    long long lbl;
    if (big == 0u)  lbl = ((const long long*)labels)[row];  // true int64 (rare)
    else            lbl = (long long)l32;                    // int32 (in flight)

    const float4* __restrict__ cr =
        reinterpret_cast<const float4*>(centers + (size_t)lbl * D_DIM);

    // ---- center row + reduction ----
    float4 c0 = cr[lane];
    float4 c1 = cr[lane + 32];
    float4 c2 = cr[lane + 64];
    float4 c3 = cr[lane + 96];

    float s = 0.0f, d;
    d = a0.x - c0.x; s = fmaf(d, d, s);
    d = a0.y - c0.y; s = fmaf(d, d, s);
    d = a0.z - c0.z; s = fmaf(d, d, s);
    d = a0.w - c0.w; s = fmaf(d, d, s);
    d = a1.x - c1.x; s = fmaf(d, d, s);
    d = a1.y - c1.y; s = fmaf(d, d, s);
    d = a1.z - c1.z; s = fmaf(d, d, s);
    d = a1.w - c1.w; s = fmaf(d, d, s);
    d = a2.x - c2.x; s = fmaf(d, d, s);
    d = a2.y - c2.y; s = fmaf(d, d, s);
    d = a2.z - c2.z; s = fmaf(d, d, s);
    d = a2.w - c2.w; s = fmaf(d, d, s);
    d = a3.x - c3.x; s = fmaf(d, d, s);
    d = a3.y - c3.y; s = fmaf(d, d, s);
    d = a3.z - c3.z; s = fmaf(d, d, s);
    d = a3.w - c3.w; s = fmaf(d, d, s);

    // warp reduce -> row distance on lane 0
    #pragma unroll
    for (int off = 16; off > 0; off >>= 1)
        s += __shfl_xor_sync(0xFFFFFFFFu, s, off);

    if (lane == 0)
        s_part[warp] = fminf(fmaxf(s, 1e-12f), 1e12f);   // per-row clamp
    __syncthreads();

    // one atomic per CTA (1024 total — measured-cheap in R3)
    if (t == 0) {
        float p = 0.0f;
        #pragma unroll
        for (int w = 0; w < WARPS_PER_CTA; w++) p += s_part[w];
        atomicAdd(out, p * (1.0f / (float)B_ROWS));
    }
}

// ---------------------------------------------------------------------------
// Launch. Inputs identified BY SIZE (robust to metadata ordering):
//   x: 4,194,304 f32 | labels: 8,192 (i32/i64, device-detected) |
//   centers: 5,120,000 f32. Output: scalar f32 (atomic-accumulated).
// ---------------------------------------------------------------------------
extern "C" void kernel_launch(void* const* d_in, const int* in_sizes, int n_in,
                              void* d_out, int out_size)
{
    const float* x       = nullptr;
    const void*  labels  = nullptr;
    const float* centers = nullptr;

    for (int i = 0; i < n_in; i++) {
        if (in_sizes[i] == B_ROWS * D_DIM)       x       = (const float*)d_in[i];
        else if (in_sizes[i] == B_ROWS)          labels  = d_in[i];
        else if (in_sizes[i] == C_ROWS * D_DIM)  centers = (const float*)d_in[i];
    }

    float* out = (float*)d_out;

    cudaMemsetAsync(out, 0, sizeof(float));   // zero accumulator each replay
    center_loss_fused<<<GRID_CTAS, 32 * WARPS_PER_CTA>>>(x, labels, centers, out);
}

// round 11
// speedup vs baseline: 1.5846x; 1.2269x over previous
#include <cuda_runtime.h>
#include <cstdint>

#define B_ROWS 8192
#define C_ROWS 10000
#define D_DIM  512
#define WARPS_PER_CTA 16
#define THREADS (32 * WARPS_PER_CTA)         // 512
#define GRID_CTAS (B_ROWS / WARPS_PER_CTA)   // 512, warp-per-row

// ---------------------------------------------------------------------------
// Warp-per-row fused kernel (proven-best body), 512-thread CTAs to halve
// the barrier/atomic drain. Barrier-free detect head, per-warp ballot.
// ---------------------------------------------------------------------------
__global__ __launch_bounds__(THREADS, 3)
void center_loss_fused(const float* __restrict__ x,
                       const void*  __restrict__ labels,
                       const float* __restrict__ centers,
                       float* __restrict__ out)
{
    __shared__ float s_part[WARPS_PER_CTA];

    const int t    = threadIdx.x;
    const int warp = t >> 5;
    const int lane = t & 31;

    const int row = blockIdx.x * WARPS_PER_CTA + warp;   // 0..8191

    // ---- head: issue everything label-independent FIRST, no barriers ----
    // dtype-detect word: first 8 u64-interpreted words (64 B, in-bounds for
    // both 8192*i32 and 8192*i64 layouts). Genuine i64 labels < 10000 keep
    // every word < 10000; a packed i32 pair exceeds 2^32 whenever the
    // odd-index label != 0 (checked over 16 labels -> certain in practice).
    unsigned long long dw = ((const unsigned long long*)labels)[lane & 7];
    // int32 interpretation: ALWAYS in-bounds, issue now (likely path).
    int l32 = ((const int*)labels)[row];

    // x row: 4 float4 per lane, label-independent, issue all now.
    const float4* __restrict__ xr =
        reinterpret_cast<const float4*>(x + (size_t)row * D_DIM);
    float4 a0 = xr[lane];
    float4 a1 = xr[lane + 32];
    float4 a2 = xr[lane + 64];
    float4 a3 = xr[lane + 96];

    // ---- resolve label (per-warp ballot; no __syncthreads) ----
    unsigned big = __ballot_sync(0xFFFFFFFFu, dw >= (unsigned long long)C_ROWS);
    long long lbl;
    if (big == 0u)  lbl = ((const long long*)labels)[row];  // true int64 (rare)
    else            lbl = (long long)l32;                    // int32 (in flight)

    const float4* __restrict__ cr =
        reinterpret_cast<const float4*>(centers + (size_t)lbl * D_DIM);

    // ---- center row + reduction ----
    float4 c0 = cr[lane];
    float4 c1 = cr[lane + 32];
    float4 c2 = cr[lane + 64];
    float4 c3 = cr[lane + 96];

    float s = 0.0f, d;
    d = a0.x - c0.x; s = fmaf(d, d, s);
    d = a0.y - c0.y; s = fmaf(d, d, s);
    d = a0.z - c0.z; s = fmaf(d, d, s);
    d = a0.w - c0.w; s = fmaf(d, d, s);
    d = a1.x - c1.x; s = fmaf(d, d, s);
    d = a1.y - c1.y; s = fmaf(d, d, s);
    d = a1.z - c1.z; s = fmaf(d, d, s);
    d = a1.w - c1.w; s = fmaf(d, d, s);
    d = a2.x - c2.x; s = fmaf(d, d, s);
    d = a2.y - c2.y; s = fmaf(d, d, s);
    d = a2.z - c2.z; s = fmaf(d, d, s);
    d = a2.w - c2.w; s = fmaf(d, d, s);
    d = a3.x - c3.x; s = fmaf(d, d, s);
    d = a3.y - c3.y; s = fmaf(d, d, s);
    d = a3.z - c3.z; s = fmaf(d, d, s);
    d = a3.w - c3.w; s = fmaf(d, d, s);

    // warp reduce -> row distance on lane 0
    #pragma unroll
    for (int off = 16; off > 0; off >>= 1)
        s += __shfl_xor_sync(0xFFFFFFFFu, s, off);

    if (lane == 0) {
        // per-row clamp, pre-scaled by 1/B
        float dist = fminf(fmaxf(s, 1e-12f), 1e12f);
        s_part[warp] = dist * (1.0f / (float)B_ROWS);
    }
    __syncthreads();

    // one atomic per CTA (512 total)
    if (t == 0) {
        float p = 0.0f;
        #pragma unroll
        for (int w = 0; w < WARPS_PER_CTA; w++) p += s_part[w];
        atomicAdd(out, p);
    }
}

// ---------------------------------------------------------------------------
// Launch. Inputs identified BY SIZE (robust to metadata ordering):
//   x: 4,194,304 f32 | labels: 8,192 (i32/i64, device-detected) |
//   centers: 5,120,000 f32. Output: scalar f32 (atomic-accumulated).
// ---------------------------------------------------------------------------
extern "C" void kernel_launch(void* const* d_in, const int* in_sizes, int n_in,
                              void* d_out, int out_size)
{
    const float* x       = nullptr;
    const void*  labels  = nullptr;
    const float* centers = nullptr;

    for (int i = 0; i < n_in; i++) {
        if (in_sizes[i] == B_ROWS * D_DIM)       x       = (const float*)d_in[i];
        else if (in_sizes[i] == B_ROWS)          labels  = d_in[i];
        else if (in_sizes[i] == C_ROWS * D_DIM)  centers = (const float*)d_in[i];
    }

    float* out = (float*)d_out;

    cudaMemsetAsync(out, 0, sizeof(float));   // zero accumulator each replay
    center_loss_fused<<<GRID_CTAS, THREADS>>>(x, labels, centers, out);
}